// round 15
// baseline (speedup 1.0000x reference)
#include <cuda_runtime.h>
#include <cuda_fp16.h>
#include <cstdint>

// ---------------- problem constants ----------------
#define NSEQ    4
#define BATCH   128
#define HID     1024
#define EMB     512
#define SEQLEN  256
#define NCTA    128
#define THREADS 320                // wid0 = A-producer, wid1 = B-producer, wid2..9 = MMA
#define NWARPS  8                  // MMA warps
#define NCH     8                  // K chunks of 128 per step (K=1024)
#define NQ      (SEQLEN * NCH)

#define IMG     16384              // one 64-K-col image: 128 rows x 128B, SW128
#define CH_A    (2*IMG)            // 32KB A per chunk (128 K-cols)
#define CH_B    (2*IMG)            // 32KB B per chunk
#define NST_A   3
#define NST_B   4
#define DYNSMEM (NST_A*CH_A + NST_B*CH_B + 1024)   // 225KB

#define NFLAG   ((SEQLEN + 1) * NSEQ * NCH)

// ---------------- persistent device buffers ----------------
// steady-state weights: [r_comb, z_comb, Wih_n, Whh_n] per (set, chunk, kc-image)
__device__ __align__(16) unsigned char g_Wb [(size_t)2*32*16*IMG]; // 16MB
// step-0 weights:       [Wih_r, Wih_z, Wih_n, zeros]
__device__ __align__(16) unsigned char g_Wb0[(size_t)2*32*16*IMG]; // 16MB
__device__ __align__(16) unsigned char g_A0[(size_t)4*16*IMG];     // x_spin images
__device__ __align__(16) unsigned char g_St[(size_t)2*4*16*IMG];   // double-buffered h images
__device__ unsigned g_flag[NFLAG];                                 // per (t, s, 128-col chunk): 4 producers

// ---------------- PTX helpers ----------------
__device__ __forceinline__ uint32_t smem_u32(const void* p) {
    uint32_t a;
    asm("{ .reg .u64 t; cvta.to.shared.u64 t, %1; cvt.u32.u64 %0, t; }" : "=r"(a) : "l"(p));
    return a;
}
__device__ __forceinline__ void mbar_init(uint32_t m, uint32_t cnt) {
    asm volatile("mbarrier.init.shared.b64 [%0], %1;" :: "r"(m), "r"(cnt) : "memory");
}
__device__ __forceinline__ void mbar_arrive_expect_tx(uint32_t m, uint32_t bytes) {
    asm volatile("mbarrier.arrive.expect_tx.shared.b64 _, [%0], %1;" :: "r"(m), "r"(bytes) : "memory");
}
__device__ __forceinline__ void mbar_arrive(uint32_t m) {
    asm volatile("mbarrier.arrive.shared.b64 _, [%0];" :: "r"(m) : "memory");
}
__device__ __forceinline__ void mbar_wait(uint32_t m, uint32_t parity) {
    asm volatile(
        "{\n\t.reg .pred P;\n\t"
        "W_%=:\n\t"
        "mbarrier.try_wait.parity.shared::cta.b64 P, [%0], %1, 0x989680;\n\t"
        "@P bra.uni D_%=;\n\t"
        "bra.uni W_%=;\n\t"
        "D_%=:\n\t}"
        :: "r"(m), "r"(parity) : "memory");
}
__device__ __forceinline__ void bulk_copy(uint32_t dst, const void* src, uint32_t bytes, uint32_t m) {
    asm volatile(
        "cp.async.bulk.shared::cluster.global.mbarrier::complete_tx::bytes [%0], [%1], %2, [%3];"
        :: "r"(dst), "l"(src), "r"(bytes), "r"(m) : "memory");
}
__device__ __forceinline__ void ldsm4(uint32_t* r, uint32_t a) {
    asm volatile("ldmatrix.sync.aligned.m8n8.x4.shared.b16 {%0,%1,%2,%3}, [%4];"
                 : "=r"(r[0]), "=r"(r[1]), "=r"(r[2]), "=r"(r[3]) : "r"(a));
}
__device__ __forceinline__ void mma16816(float* d, const uint32_t* a, const uint32_t* b) {
    asm("mma.sync.aligned.m16n8k16.row.col.f32.f16.f16.f32 "
        "{%0,%1,%2,%3}, {%4,%5,%6,%7}, {%8,%9}, {%0,%1,%2,%3};"
        : "+f"(d[0]), "+f"(d[1]), "+f"(d[2]), "+f"(d[3])
        : "r"(a[0]), "r"(a[1]), "r"(a[2]), "r"(a[3]), "r"(b[0]), "r"(b[1]));
}

__device__ __forceinline__ float sigm(float x) {
    return __fdividef(1.0f, 1.0f + __expf(-x));
}
__device__ __forceinline__ float tanh_fast(float x) {
    return 1.0f - __fdividef(2.0f, 1.0f + __expf(2.0f * x));
}
__device__ __forceinline__ unsigned short us16(__half v) {
    return reinterpret_cast<unsigned short&>(v);
}
__device__ __forceinline__ uint32_t sw128(uint32_t off) { return off ^ ((off >> 3) & 0x70); }

// ---------------- fused prologue: weights (2 blobs) + x images + flag clear ----
__global__ void prep_all(const float* __restrict__ Wih_up, const float* __restrict__ Whh_up,
                         const float* __restrict__ Wih_dn, const float* __restrict__ Whh_dn,
                         const float* __restrict__ x) {
    int b = blockIdx.x;
    if (b < 2048) {                          // weight images (steady + t0), 64-col granularity
        int t0    = (b >> 10) & 1;
        int bb    = b & 1023;
        int set   = bb >> 9;
        int chunk = (bb >> 4) & 31;
        int kc    = bb & 15;
        const float* Wih = set ? Wih_dn : Wih_up;
        const float* Whh = set ? Whh_dn : Whh_up;
        unsigned char* img = (t0 ? g_Wb0 : g_Wb)
                           + ((size_t)((set * 32 + chunk) * 16 + kc)) * IMG;
        for (int e = threadIdx.x; e < 128 * 64; e += blockDim.x) {
            int n = e >> 6, col = e & 63;
            int g = n >> 5, jj = n & 31;     // 4 gate groups x 32 cols
            size_t roff = (size_t)(chunk * 32 + jj) * HID + kc * 64 + col;
            float v;
            if (!t0) {   // steady: [Wr+Whr, Wz+Whz, Win, Whn]
                if (g < 2)      v = Wih[(size_t)g * HID * HID + roff] + Whh[(size_t)g * HID * HID + roff];
                else if (g == 2) v = Wih[(size_t)2 * HID * HID + roff];
                else             v = Whh[(size_t)2 * HID * HID + roff];
            } else {     // t0: [Wr, Wz, Wn, 0]
                v = (g < 3) ? Wih[(size_t)g * HID * HID + roff] : 0.0f;
            }
            *(__half*)(img + sw128((uint32_t)(n * 128 + col * 2))) = __float2half_rn(v);
        }
    } else if (b < 2112) {                   // x_spin images: 64 = s*16 + kc
        int bb = b - 2048;
        int s = bb >> 4, kc = bb & 15;
        unsigned char* img = g_A0 + (size_t)(s * 16 + kc) * IMG;
        for (int e = threadIdx.x; e < 128 * 64; e += blockDim.x) {
            int m = e >> 6, col = e & 63;
            int gc = kc * 64 + col;
            float v = x[m * EMB + (gc & (EMB - 1))];
            if ((s & 1) && gc >= EMB) v = -v;
            *(__half*)(img + sw128((uint32_t)(m * 128 + col * 2))) = __float2half_rn(v);
        }
    } else {                                 // flag clear (graph-replay determinism)
        int idx = (b - 2112) * 256 + threadIdx.x;
        if (idx < NFLAG) g_flag[idx] = 0;
    }
}

// ---------------- persistent HMMA GRU kernel: split A/B producer warps ----------
__global__ __launch_bounds__(THREADS, 1)
void gru_mma_kernel(const float* __restrict__ bih_up, const float* __restrict__ bhh_up,
                    const float* __restrict__ bih_dn, const float* __restrict__ bhh_dn,
                    float* __restrict__ out) {
    extern __shared__ __align__(16) unsigned char dynsmem[];
    __shared__ __align__(8) unsigned long long s_mbar[2 * (NST_A + NST_B)];

    const int tid  = threadIdx.x;
    const int lane = tid & 31;
    const int wid  = tid >> 5;

    const int s     = blockIdx.x >> 5;
    const int chunk = blockIdx.x & 31;
    const int wset  = s >> 1;
    const int c0    = chunk * 32;

    const uint32_t mb = smem_u32(s_mbar);
    uint32_t fulA[NST_A], empA[NST_A], fulB[NST_B], empB[NST_B];
#pragma unroll
    for (int i = 0; i < NST_A; i++) { fulA[i] = mb + 8 * i;              empA[i] = mb + 8 * (NST_A + i); }
#pragma unroll
    for (int i = 0; i < NST_B; i++) { fulB[i] = mb + 8 * (2 * NST_A + i); empB[i] = mb + 8 * (2 * NST_A + NST_B + i); }
    if (tid == 0) {
#pragma unroll
        for (int i = 0; i < NST_A; i++) { mbar_init(fulA[i], 1); mbar_init(empA[i], NWARPS); }
#pragma unroll
        for (int i = 0; i < NST_B; i++) { mbar_init(fulB[i], 1); mbar_init(empB[i], NWARPS); }
    }
    __syncthreads();   // ONLY full-CTA barrier; producer warps never sync again

    const uint32_t smA0 = (smem_u32(dynsmem) + 1023u) & ~1023u;
    const uint32_t smB0 = smA0 + NST_A * CH_A;
    const size_t wb_off = (size_t)(wset * 32 + chunk) * 16 * IMG;

    // ===== A-producer warp (wid 0, lowest priority on SMSP0) =====
    if (wid == 0) {
        if (lane == 0) {
            for (int q = 0; q < NQ; ++q) {
                const int t  = q >> 3;
                const int kc = q & 7;
                const int st = q % NST_A;
                if (q >= NST_A)
                    mbar_wait(empA[st], (uint32_t)(((q - NST_A) / NST_A) & 1));
                if (t > 0) {
                    volatile unsigned* f = &g_flag[(t * NSEQ + s) * NCH + kc];
                    while (*f < 4u) { __nanosleep(128); }
                    asm volatile("fence.proxy.async.global;" ::: "memory");
                }
                const unsigned char* Ab = (t == 0)
                    ? (g_A0 + (size_t)s * 16 * IMG)
                    : (g_St + (size_t)((t & 1) * 4 + s) * 16 * IMG);
                mbar_arrive_expect_tx(fulA[st], CH_A);
                bulk_copy(smA0 + (uint32_t)st * CH_A,
                          Ab + (size_t)kc * CH_A, CH_A, fulA[st]);
            }
        }
        return;
    }

    // ===== B-producer warp (wid 1, lowest priority on SMSP1): flag-free =====
    if (wid == 1) {
        if (lane == 0) {
            const unsigned char* Wblob  = g_Wb  + wb_off;
            const unsigned char* Wblob0 = g_Wb0 + wb_off;
            for (int q = 0; q < NQ; ++q) {
                const int t  = q >> 3;
                const int kc = q & 7;
                const int st = q % NST_B;
                if (q >= NST_B)
                    mbar_wait(empB[st], (uint32_t)(((q - NST_B) / NST_B) & 1));
                const unsigned char* blob = t ? Wblob : Wblob0;
                mbar_arrive_expect_tx(fulB[st], CH_B);
                bulk_copy(smB0 + (uint32_t)st * CH_B,
                          blob + (size_t)kc * CH_B, CH_B, fulB[st]);
            }
        }
        return;
    }

    // ================= MMA warps (wid 2..9) =================
    const int mwid = wid - 2;          // 0..7
    const int wm = mwid >> 2;          // 0..1  (M half)
    const int wn = mwid & 3;           // 0..3  (j-oct)

    const float* bih = wset ? bih_dn : bih_up;
    const float* bhh = wset ? bhh_dn : bhh_up;

    const int j0  = wn * 8 + 2 * (lane & 3);
    const int jg  = c0 + j0;
    const float bR0 = bih[jg]     + bhh[jg];
    const float bR1 = bih[jg + 1] + bhh[jg + 1];
    const float bZ0 = bih[HID + jg]     + bhh[HID + jg];
    const float bZ1 = bih[HID + jg + 1] + bhh[HID + jg + 1];
    const float bI0 = bih[2 * HID + jg],     bI1 = bih[2 * HID + jg + 1];
    const float bH0 = bhh[2 * HID + jg],     bH1 = bhh[2 * HID + jg + 1];

    // A ldmatrix addressing (64 rows per warp, 4 m16 tiles)
    const int rowA  = wm * 64 + (lane & 15);
    const uint32_t axor = (uint32_t)((rowA & 7) << 4);
    const uint32_t aklane = (uint32_t)((lane >> 4) * 16);
    uint32_t arow[4];
#pragma unroll
    for (int mt = 0; mt < 4; mt++) arow[mt] = (uint32_t)((rowA + mt * 16) * 128);

    // B ldmatrix: gate-pair packed x4. Lanes 0-15 -> gate 2p, lanes 16-31 -> gate 2p+1.
    const int rowB2 = wn * 8 + (lane & 7) + ((lane >> 4) & 1) * 32;
    const uint32_t bxor = (uint32_t)((lane & 7) << 4);
    const uint32_t bklane = (uint32_t)(((lane >> 3) & 1) * 16);
    uint32_t brow[2];
#pragma unroll
    for (int p = 0; p < 2; p++) brow[p] = (uint32_t)((rowB2 + p * 64) * 128);

    float h[16];
#pragma unroll
    for (int i = 0; i < 16; i++) h[i] = 0.0f;

    for (int t = 0; t < SEQLEN; ++t) {
        float acc[4][4][4];   // [m-tile][gate group][frag]
#pragma unroll
        for (int mt = 0; mt < 4; mt++)
#pragma unroll
            for (int g = 0; g < 4; g++)
#pragma unroll
                for (int r = 0; r < 4; r++) acc[mt][g][r] = 0.0f;

        for (int kc = 0; kc < NCH; ++kc) {
            const int q = t * NCH + kc;
            const int stA = q % NST_A;
            const int stB = q % NST_B;
            mbar_wait(fulA[stA], (uint32_t)((q / NST_A) & 1));
            mbar_wait(fulB[stB], (uint32_t)((q / NST_B) & 1));
            const uint32_t sAh = smA0 + (uint32_t)stA * CH_A;
            const uint32_t sBh = smB0 + (uint32_t)stB * CH_B;

#pragma unroll
            for (int kk = 0; kk < 8; ++kk) {          // 8 x 16 K-cols = 128
                const uint32_t imoff = (uint32_t)(kk >> 2) * IMG;
                const uint32_t ak = ((uint32_t)((kk & 3) * 32) + aklane) ^ axor;
                const uint32_t bk = ((uint32_t)((kk & 3) * 32) + bklane) ^ bxor;
                uint32_t ah[4][4], bfr[2][4];
#pragma unroll
                for (int mt = 0; mt < 4; mt++) ldsm4(ah[mt], sAh + imoff + arow[mt] + ak);
#pragma unroll
                for (int p = 0; p < 2; p++) ldsm4(bfr[p], sBh + imoff + brow[p] + bk);

#pragma unroll
                for (int p = 0; p < 2; p++)
#pragma unroll
                    for (int gp = 0; gp < 2; gp++) {
                        const int g = 2 * p + gp;
                        const uint32_t* bf = &bfr[p][2 * gp];
#pragma unroll
                        for (int mt = 0; mt < 4; mt++)
                            mma16816(acc[mt][g], ah[mt], bf);
                    }
            }
            if (lane == 0) { mbar_arrive(empA[stA]); mbar_arrive(empB[stB]); }
        }

        // ---------------- epilogue: lane-local gate fusion (uniform for all t) ----
        unsigned char* Sbase = g_St + ((size_t)(((t + 1) & 1) * 4 + s) * 16 + (chunk >> 1)) * IMG;
        const uint32_t colbyte = (uint32_t)(((chunk & 1) * 32 + j0) * 2);

#pragma unroll
        for (int mt = 0; mt < 4; mt++) {
#pragma unroll
            for (int rr = 0; rr < 2; rr++) {
                const int ri = rr * 2;
                const int m  = wm * 64 + mt * 16 + rr * 8 + (lane >> 2);
                float r0 = sigm(acc[mt][0][ri]     + bR0);
                float r1 = sigm(acc[mt][0][ri + 1] + bR1);
                float z0 = sigm(acc[mt][1][ri]     + bZ0);
                float z1 = sigm(acc[mt][1][ri + 1] + bZ1);
                float n0 = tanh_fast(acc[mt][2][ri]     + bI0 + r0 * (acc[mt][3][ri]     + bH0));
                float n1 = tanh_fast(acc[mt][2][ri + 1] + bI1 + r1 * (acc[mt][3][ri + 1] + bH1));
                const int idx = mt * 4 + rr * 2;
                float v0 = (1.0f - z0) * n0 + z0 * h[idx];
                float v1 = (1.0f - z1) * n1 + z1 * h[idx + 1];
                h[idx] = v0; h[idx + 1] = v1;

                *reinterpret_cast<float2*>(
                    out + ((size_t)(s * BATCH + m) * SEQLEN + t) * HID + jg) = make_float2(v0, v1);

                __half h0 = __float2half_rn(v0);
                __half h1 = __float2half_rn(v1);
                uint32_t hip = (uint32_t)us16(h0) | ((uint32_t)us16(h1) << 16);
                uint32_t sw = sw128((uint32_t)(m * 128) + colbyte);
                *reinterpret_cast<uint32_t*>(Sbase + sw) = hip;
            }
        }

        // publish among the 8 MMA warps only (named barrier; producers never join)
        __threadfence();
        asm volatile("bar.sync 1, 256;" ::: "memory");
        if (tid == 64 && t + 1 < SEQLEN)      // MMA warp (wid 2), lane 0
            atomicAdd(&g_flag[((t + 1) * NSEQ + s) * NCH + (chunk >> 2)], 1u);
    }
}

extern "C" void kernel_launch(void* const* d_in, const int* in_sizes, int n_in,
                              void* d_out, int out_size) {
    const float* x      = (const float*)d_in[0];
    const float* Wih_up = (const float*)d_in[1];
    const float* Whh_up = (const float*)d_in[2];
    const float* Wih_dn = (const float*)d_in[3];
    const float* Whh_dn = (const float*)d_in[4];
    const float* bih_up = (const float*)d_in[5];
    const float* bhh_up = (const float*)d_in[6];
    const float* bih_dn = (const float*)d_in[7];
    const float* bhh_dn = (const float*)d_in[8];
    float* out = (float*)d_out;

    cudaFuncSetAttribute(gru_mma_kernel, cudaFuncAttributeMaxDynamicSharedMemorySize, DYNSMEM);

    // 2048 weight blocks + 64 x-image blocks + 33 flag-clear blocks
    prep_all<<<2145, 256>>>(Wih_up, Whh_up, Wih_dn, Whh_dn, x);
    gru_mma_kernel<<<NCTA, THREADS, DYNSMEM>>>(bih_up, bhh_up, bih_dn, bhh_dn, out);
}

// round 16
// speedup vs baseline: 1.0429x; 1.0429x over previous
#include <cuda_runtime.h>
#include <cuda_fp16.h>
#include <cstdint>

// ---------------- problem constants ----------------
#define NSEQ    4
#define BATCH   128
#define HID     1024
#define EMB     512
#define SEQLEN  256
#define NCTA    128
#define THREADS 288                // wid0 = producer (lowest priority), wid1..8 = MMA
#define NWARPS  8                  // MMA warps
#define NCH     8                  // K chunks of 128 per step (K=1024)

#define IMG     16384              // one 64-K-col image: 128 rows x 128B, SW128
#define CH_A    (2*IMG)            // 32KB A per chunk (128 K-cols)
#define CH_B    (2*IMG)            // 32KB B per chunk
#define STAGE   (CH_A + CH_B)      // 64KB
#define NSTAGE  3
#define DYNSMEM (NSTAGE*STAGE + 1024)

#define NFLAG   ((SEQLEN + 1) * NSEQ * NCH)
#define FLAG_GOAL 32u              // 8 warps x 4 producer CTAs

// ---------------- persistent device buffers ----------------
// steady-state weights: [r_comb, z_comb, Wih_n, Whh_n] per (set, chunk, kc-image)
__device__ __align__(16) unsigned char g_Wb [(size_t)2*32*16*IMG]; // 16MB
// step-0 weights:       [Wih_r, Wih_z, Wih_n, zeros]
__device__ __align__(16) unsigned char g_Wb0[(size_t)2*32*16*IMG]; // 16MB
__device__ __align__(16) unsigned char g_A0[(size_t)4*16*IMG];     // x_spin images
__device__ __align__(16) unsigned char g_St[(size_t)2*4*16*IMG];   // double-buffered h images
__device__ unsigned g_flag[NFLAG];                                 // per (t, s, 128-col chunk)

// ---------------- PTX helpers ----------------
__device__ __forceinline__ uint32_t smem_u32(const void* p) {
    uint32_t a;
    asm("{ .reg .u64 t; cvta.to.shared.u64 t, %1; cvt.u32.u64 %0, t; }" : "=r"(a) : "l"(p));
    return a;
}
__device__ __forceinline__ void mbar_init(uint32_t m, uint32_t cnt) {
    asm volatile("mbarrier.init.shared.b64 [%0], %1;" :: "r"(m), "r"(cnt) : "memory");
}
__device__ __forceinline__ void mbar_arrive_expect_tx(uint32_t m, uint32_t bytes) {
    asm volatile("mbarrier.arrive.expect_tx.shared.b64 _, [%0], %1;" :: "r"(m), "r"(bytes) : "memory");
}
__device__ __forceinline__ void mbar_arrive(uint32_t m) {
    asm volatile("mbarrier.arrive.shared.b64 _, [%0];" :: "r"(m) : "memory");
}
__device__ __forceinline__ void mbar_wait(uint32_t m, uint32_t parity) {
    asm volatile(
        "{\n\t.reg .pred P;\n\t"
        "W_%=:\n\t"
        "mbarrier.try_wait.parity.shared::cta.b64 P, [%0], %1, 0x989680;\n\t"
        "@P bra.uni D_%=;\n\t"
        "bra.uni W_%=;\n\t"
        "D_%=:\n\t}"
        :: "r"(m), "r"(parity) : "memory");
}
__device__ __forceinline__ void bulk_copy(uint32_t dst, const void* src, uint32_t bytes, uint32_t m) {
    asm volatile(
        "cp.async.bulk.shared::cluster.global.mbarrier::complete_tx::bytes [%0], [%1], %2, [%3];"
        :: "r"(dst), "l"(src), "r"(bytes), "r"(m) : "memory");
}
__device__ __forceinline__ void ldsm4(uint32_t* r, uint32_t a) {
    asm volatile("ldmatrix.sync.aligned.m8n8.x4.shared.b16 {%0,%1,%2,%3}, [%4];"
                 : "=r"(r[0]), "=r"(r[1]), "=r"(r[2]), "=r"(r[3]) : "r"(a));
}
__device__ __forceinline__ void mma16816(float* d, const uint32_t* a, const uint32_t* b) {
    asm("mma.sync.aligned.m16n8k16.row.col.f32.f16.f16.f32 "
        "{%0,%1,%2,%3}, {%4,%5,%6,%7}, {%8,%9}, {%0,%1,%2,%3};"
        : "+f"(d[0]), "+f"(d[1]), "+f"(d[2]), "+f"(d[3])
        : "r"(a[0]), "r"(a[1]), "r"(a[2]), "r"(a[3]), "r"(b[0]), "r"(b[1]));
}

__device__ __forceinline__ float sigm(float x) {
    return __fdividef(1.0f, 1.0f + __expf(-x));
}
__device__ __forceinline__ float tanh_fast(float x) {
    return 1.0f - __fdividef(2.0f, 1.0f + __expf(2.0f * x));
}
__device__ __forceinline__ unsigned short us16(__half v) {
    return reinterpret_cast<unsigned short&>(v);
}
__device__ __forceinline__ uint32_t sw128(uint32_t off) { return off ^ ((off >> 3) & 0x70); }

// ---------------- fused prologue: weights (2 blobs) + x images + flag clear ----
__global__ void prep_all(const float* __restrict__ Wih_up, const float* __restrict__ Whh_up,
                         const float* __restrict__ Wih_dn, const float* __restrict__ Whh_dn,
                         const float* __restrict__ x) {
    int b = blockIdx.x;
    if (b < 2048) {                          // weight images (steady + t0), 64-col granularity
        int t0    = (b >> 10) & 1;
        int bb    = b & 1023;
        int set   = bb >> 9;
        int chunk = (bb >> 4) & 31;
        int kc    = bb & 15;
        const float* Wih = set ? Wih_dn : Wih_up;
        const float* Whh = set ? Whh_dn : Whh_up;
        unsigned char* img = (t0 ? g_Wb0 : g_Wb)
                           + ((size_t)((set * 32 + chunk) * 16 + kc)) * IMG;
        for (int e = threadIdx.x; e < 128 * 64; e += blockDim.x) {
            int n = e >> 6, col = e & 63;
            int g = n >> 5, jj = n & 31;     // 4 gate groups x 32 cols
            size_t roff = (size_t)(chunk * 32 + jj) * HID + kc * 64 + col;
            float v;
            if (!t0) {   // steady: [Wr+Whr, Wz+Whz, Win, Whn]
                if (g < 2)      v = Wih[(size_t)g * HID * HID + roff] + Whh[(size_t)g * HID * HID + roff];
                else if (g == 2) v = Wih[(size_t)2 * HID * HID + roff];
                else             v = Whh[(size_t)2 * HID * HID + roff];
            } else {     // t0: [Wr, Wz, Wn, 0]
                v = (g < 3) ? Wih[(size_t)g * HID * HID + roff] : 0.0f;
            }
            *(__half*)(img + sw128((uint32_t)(n * 128 + col * 2))) = __float2half_rn(v);
        }
    } else if (b < 2112) {                   // x_spin images: 64 = s*16 + kc
        int bb = b - 2048;
        int s = bb >> 4, kc = bb & 15;
        unsigned char* img = g_A0 + (size_t)(s * 16 + kc) * IMG;
        for (int e = threadIdx.x; e < 128 * 64; e += blockDim.x) {
            int m = e >> 6, col = e & 63;
            int gc = kc * 64 + col;
            float v = x[m * EMB + (gc & (EMB - 1))];
            if ((s & 1) && gc >= EMB) v = -v;
            *(__half*)(img + sw128((uint32_t)(m * 128 + col * 2))) = __float2half_rn(v);
        }
    } else {                                 // flag clear (graph-replay determinism)
        int idx = (b - 2112) * 256 + threadIdx.x;
        if (idx < NFLAG) g_flag[idx] = 0;
    }
}

// ---------------- persistent HMMA GRU kernel: low-priority producer warp ----
__global__ __launch_bounds__(THREADS, 1)
void gru_mma_kernel(const float* __restrict__ bih_up, const float* __restrict__ bhh_up,
                    const float* __restrict__ bih_dn, const float* __restrict__ bhh_dn,
                    float* __restrict__ out) {
    extern __shared__ __align__(16) unsigned char dynsmem[];
    __shared__ __align__(8) unsigned long long s_mbar[2 * NSTAGE];  // full[3], emp[3]

    const int tid  = threadIdx.x;
    const int lane = tid & 31;
    const int wid  = tid >> 5;

    const int s     = blockIdx.x >> 5;
    const int chunk = blockIdx.x & 31;
    const int wset  = s >> 1;
    const int c0    = chunk * 32;

    const uint32_t mb = smem_u32(s_mbar);
    uint32_t mb_full[NSTAGE], mb_emp[NSTAGE];
#pragma unroll
    for (int i = 0; i < NSTAGE; i++) { mb_full[i] = mb + 8 * i; mb_emp[i] = mb + 8 * (NSTAGE + i); }
    if (tid == 0) {
#pragma unroll
        for (int i = 0; i < NSTAGE; i++) {
            mbar_init(mb_full[i], 2);        // one arrive from B-push, one from A-push
            mbar_init(mb_emp[i], NWARPS);    // one arrive per MMA warp (lane 0)
        }
    }
    __syncthreads();   // ONLY full-CTA barrier

    const uint32_t sm0 = (smem_u32(dynsmem) + 1023u) & ~1023u;
    const size_t wb_off = (size_t)(wset * 32 + chunk) * 16 * IMG;

    // ===== producer warp (wid 0: LOWEST arbiter priority): free-running scan =====
    if (wid == 0) {
        if (lane == 0) {
            const unsigned char* Wblob  = g_Wb  + wb_off;
            const unsigned char* Wblob0 = g_Wb0 + wb_off;
            for (int q = 0; q < SEQLEN * NCH; ++q) {
                const int t  = q >> 3;
                const int kc = q & 7;
                const int st = q % NSTAGE;
                if (q >= NSTAGE)
                    mbar_wait(mb_emp[st], (uint32_t)(((q - NSTAGE) / NSTAGE) & 1));
                // B first (no dependency on flags)
                const unsigned char* blob = t ? Wblob : Wblob0;
                mbar_arrive_expect_tx(mb_full[st], CH_B);
                bulk_copy(sm0 + (uint32_t)st * STAGE + CH_A,
                          blob + (size_t)kc * CH_B, CH_B, mb_full[st]);
                // A: poll (with backoff) the 32 producer warps of this 128-col chunk
                if (t > 0) {
                    volatile unsigned* f = &g_flag[(t * NSEQ + s) * NCH + kc];
                    while (*f < FLAG_GOAL) { __nanosleep(64); }
                    asm volatile("fence.proxy.async.global;" ::: "memory");
                }
                const unsigned char* Ab = (t == 0)
                    ? (g_A0 + (size_t)s * 16 * IMG)
                    : (g_St + (size_t)((t & 1) * 4 + s) * 16 * IMG);
                mbar_arrive_expect_tx(mb_full[st], CH_A);
                bulk_copy(sm0 + (uint32_t)st * STAGE,
                          Ab + (size_t)kc * CH_A, CH_A, mb_full[st]);
            }
        }
        return;   // producer warp exits the MMA path
    }

    // ================= MMA warps (wid 1..8) =================
    const int mwid = wid - 1;          // 0..7
    const int wm = mwid >> 2;          // 0..1  (M half)
    const int wn = mwid & 3;           // 0..3  (j-oct)

    const float* bih = wset ? bih_dn : bih_up;
    const float* bhh = wset ? bhh_dn : bhh_up;

    const int j0  = wn * 8 + 2 * (lane & 3);
    const int jg  = c0 + j0;
    const float bR0 = bih[jg]     + bhh[jg];
    const float bR1 = bih[jg + 1] + bhh[jg + 1];
    const float bZ0 = bih[HID + jg]     + bhh[HID + jg];
    const float bZ1 = bih[HID + jg + 1] + bhh[HID + jg + 1];
    const float bI0 = bih[2 * HID + jg],     bI1 = bih[2 * HID + jg + 1];
    const float bH0 = bhh[2 * HID + jg],     bH1 = bhh[2 * HID + jg + 1];

    // A ldmatrix addressing (64 rows per warp, 4 m16 tiles)
    const int rowA  = wm * 64 + (lane & 15);
    const uint32_t axor = (uint32_t)((rowA & 7) << 4);
    const uint32_t aklane = (uint32_t)((lane >> 4) * 16);
    uint32_t arow[4];
#pragma unroll
    for (int mt = 0; mt < 4; mt++) arow[mt] = (uint32_t)((rowA + mt * 16) * 128);

    // B ldmatrix: gate-pair packed x4. Lanes 0-15 -> gate 2p, lanes 16-31 -> gate 2p+1.
    const int rowB2 = wn * 8 + (lane & 7) + ((lane >> 4) & 1) * 32;
    const uint32_t bxor = (uint32_t)((lane & 7) << 4);
    const uint32_t bklane = (uint32_t)(((lane >> 3) & 1) * 16);
    uint32_t brow[2];
#pragma unroll
    for (int p = 0; p < 2; p++) brow[p] = (uint32_t)((rowB2 + p * 64) * 128);

    float h[16];
#pragma unroll
    for (int i = 0; i < 16; i++) h[i] = 0.0f;

    for (int t = 0; t < SEQLEN; ++t) {
        float acc[4][4][4];   // [m-tile][gate group][frag]
#pragma unroll
        for (int mt = 0; mt < 4; mt++)
#pragma unroll
            for (int g = 0; g < 4; g++)
#pragma unroll
                for (int r = 0; r < 4; r++) acc[mt][g][r] = 0.0f;

        for (int kc = 0; kc < NCH; ++kc) {
            const int q = t * NCH + kc;
            const int st = q % NSTAGE;
            mbar_wait(mb_full[st], (uint32_t)((q / NSTAGE) & 1));
            const uint32_t sAh = sm0 + (uint32_t)st * STAGE;
            const uint32_t sBh = sAh + CH_A;

#pragma unroll
            for (int kk = 0; kk < 8; ++kk) {          // 8 x 16 K-cols = 128
                const uint32_t imoff = (uint32_t)(kk >> 2) * IMG;
                const uint32_t ak = ((uint32_t)((kk & 3) * 32) + aklane) ^ axor;
                const uint32_t bk = ((uint32_t)((kk & 3) * 32) + bklane) ^ bxor;
                uint32_t ah[4][4], bfr[2][4];
#pragma unroll
                for (int mt = 0; mt < 4; mt++) ldsm4(ah[mt], sAh + imoff + arow[mt] + ak);
#pragma unroll
                for (int p = 0; p < 2; p++) ldsm4(bfr[p], sBh + imoff + brow[p] + bk);

#pragma unroll
                for (int p = 0; p < 2; p++)
#pragma unroll
                    for (int gp = 0; gp < 2; gp++) {
                        const int g = 2 * p + gp;
                        const uint32_t* bf = &bfr[p][2 * gp];
#pragma unroll
                        for (int mt = 0; mt < 4; mt++)
                            mma16816(acc[mt][g], ah[mt], bf);
                    }
            }
            if (lane == 0) mbar_arrive(mb_emp[st]);   // one arrive per MMA warp
        }

        // ------- epilogue phase 1: gate math + state-image stores (critical path) ----
        unsigned char* Sbase = g_St + ((size_t)(((t + 1) & 1) * 4 + s) * 16 + (chunk >> 1)) * IMG;
        const uint32_t colbyte = (uint32_t)(((chunk & 1) * 32 + j0) * 2);
        float val[16];

#pragma unroll
        for (int mt = 0; mt < 4; mt++) {
#pragma unroll
            for (int rr = 0; rr < 2; rr++) {
                const int ri = rr * 2;
                const int m  = wm * 64 + mt * 16 + rr * 8 + (lane >> 2);
                float r0 = sigm(acc[mt][0][ri]     + bR0);
                float r1 = sigm(acc[mt][0][ri + 1] + bR1);
                float z0 = sigm(acc[mt][1][ri]     + bZ0);
                float z1 = sigm(acc[mt][1][ri + 1] + bZ1);
                float n0 = tanh_fast(acc[mt][2][ri]     + bI0 + r0 * (acc[mt][3][ri]     + bH0));
                float n1 = tanh_fast(acc[mt][2][ri + 1] + bI1 + r1 * (acc[mt][3][ri + 1] + bH1));
                const int idx = mt * 4 + rr * 2;
                float v0 = (1.0f - z0) * n0 + z0 * h[idx];
                float v1 = (1.0f - z1) * n1 + z1 * h[idx + 1];
                h[idx] = v0; h[idx + 1] = v1;
                val[idx] = v0; val[idx + 1] = v1;

                __half h0 = __float2half_rn(v0);
                __half h1 = __float2half_rn(v1);
                uint32_t hip = (uint32_t)us16(h0) | ((uint32_t)us16(h1) << 16);
                uint32_t sw = sw128((uint32_t)(m * 128) + colbyte);
                *reinterpret_cast<uint32_t*>(Sbase + sw) = hip;
            }
        }

        // ------- publish per warp: no CTA barrier; threshold = 32 warps ----------
        __threadfence();
        if (lane == 0 && t + 1 < SEQLEN)
            atomicAdd(&g_flag[((t + 1) * NSEQ + s) * NCH + (chunk >> 2)], 1u);

        // ------- epilogue phase 2: output stores (off the critical path) ---------
#pragma unroll
        for (int mt = 0; mt < 4; mt++) {
#pragma unroll
            for (int rr = 0; rr < 2; rr++) {
                const int idx = mt * 4 + rr * 2;
                const int m   = wm * 64 + mt * 16 + rr * 8 + (lane >> 2);
                *reinterpret_cast<float2*>(
                    out + ((size_t)(s * BATCH + m) * SEQLEN + t) * HID + jg)
                    = make_float2(val[idx], val[idx + 1]);
            }
        }
    }
}

extern "C" void kernel_launch(void* const* d_in, const int* in_sizes, int n_in,
                              void* d_out, int out_size) {
    const float* x      = (const float*)d_in[0];
    const float* Wih_up = (const float*)d_in[1];
    const float* Whh_up = (const float*)d_in[2];
    const float* Wih_dn = (const float*)d_in[3];
    const float* Whh_dn = (const float*)d_in[4];
    const float* bih_up = (const float*)d_in[5];
    const float* bhh_up = (const float*)d_in[6];
    const float* bih_dn = (const float*)d_in[7];
    const float* bhh_dn = (const float*)d_in[8];
    float* out = (float*)d_out;

    cudaFuncSetAttribute(gru_mma_kernel, cudaFuncAttributeMaxDynamicSharedMemorySize, DYNSMEM);

    // 2048 weight blocks + 64 x-image blocks + 33 flag-clear blocks
    prep_all<<<2145, 256>>>(Wih_up, Whh_up, Wih_dn, Whh_dn, x);
    gru_mma_kernel<<<NCTA, THREADS, DYNSMEM>>>(bih_up, bhh_up, bih_dn, bhh_dn, out);
}